// round 7
// baseline (speedup 1.0000x reference)
#include <cuda_runtime.h>
#include <cuda_bf16.h>

static constexpr int M_GT = 64;
static constexpr int BLOCK = 256;
#define TH (1.0f / 3.0f)   // iou >= 0.5  <=>  u = inter/S >= 1/3

__global__ void __launch_bounds__(BLOCK, 6)
roihead_kernel(const float4* __restrict__ proposals,   // [B, N] float4
               const float4* __restrict__ gt_boxes,    // [B, 64] float4
               const float4* __restrict__ deltas,      // [B, N] float4
               float4* __restrict__ out_decoded,
               float4* __restrict__ out_targets,
               float*  __restrict__ out_matches,
               int N)
{
    __shared__ float4 s_g[M_GT];
    __shared__ float  s_area[M_GT];

    const int b = blockIdx.y;

    if (threadIdx.x < M_GT) {
        float4 g = gt_boxes[b * M_GT + threadIdx.x];
        s_g[threadIdx.x] = g;
        s_area[threadIdx.x] = (g.z - g.x) * (g.w - g.y);
    }
    __syncthreads();

    // Lane pair (2m, 2m+1) cooperates on proposals n0=2m, n1=2m+1.
    // h selects the interleaved gt subset g = 2i+h (2-address broadcast LDS).
    const int t = blockIdx.x * BLOCK + threadIdx.x;
    const int m = t >> 1;
    const int h = t & 1;

    const int n0 = 2 * m;
    const int n1 = 2 * m + 1;
    const bool v0 = (n0 < N);
    const bool v1 = (n1 < N);

    const long base = (long)b * N;
    const long idx0 = base + (v0 ? n0 : 0);
    const long idx1 = base + (v1 ? n1 : 0);

    const float4 p0 = proposals[idx0];
    const float4 p1 = proposals[idx1];
    const float areap0 = (p0.z - p0.x) * (p0.w - p0.y);
    const float areap1 = (p1.z - p1.x) * (p1.w - p1.y);

    float best0 = -1.0f, best1 = -1.0f;
    int   bi0   = 0,     bi1   = 0;

#pragma unroll 16
    for (int i = 0; i < M_GT / 2; ++i) {
        const int g = 2 * i + h;
        const float4 gb = s_g[g];
        const float  ag = s_area[g];

        {   // proposal n0 : u = inter / (area_g + area_p)  (monotone in iou)
            const float iw = fminf(gb.z, p0.z) - fmaxf(gb.x, p0.x);   // unclamped (safe, R4)
            const float ih = fmaxf(fminf(gb.w, p0.w) - fmaxf(gb.y, p0.y), 0.0f);
            const float u  = __fdividef(iw * ih, ag + areap0);
            if (u > best0) { best0 = u; bi0 = g; }    // full-precision first-max
        }
        {   // proposal n1
            const float iw = fminf(gb.z, p1.z) - fmaxf(gb.x, p1.x);
            const float ih = fmaxf(fminf(gb.w, p1.w) - fmaxf(gb.y, p1.y), 0.0f);
            const float u  = __fdividef(iw * ih, ag + areap1);
            if (u > best1) { best1 = u; bi1 = g; }
        }
    }

    // Merge across the lane pair (exact first-max: tie -> lower g).
    {
        const float ob  = __shfl_xor_sync(0xFFFFFFFFu, best0, 1);
        const int   obi = __shfl_xor_sync(0xFFFFFFFFu, bi0,   1);
        if (ob > best0 || (ob == best0 && obi < bi0)) { best0 = ob; bi0 = obi; }
    }
    {
        const float ob  = __shfl_xor_sync(0xFFFFFFFFu, best1, 1);
        const int   obi = __shfl_xor_sync(0xFFFFFFFFu, bi1,   1);
        if (ob > best1 || (ob == best1 && obi < bi1)) { best1 = ob; bi1 = obi; }
    }

    // Convergent epilogue: lane h writes proposal n_h.
    const float4 p    = h ? p1    : p0;
    const float  best = h ? best1 : best0;
    const int    bi   = h ? bi1   : bi0;
    const long   idx  = h ? idx1  : idx0;
    const bool   v    = h ? v1    : v0;

    if (v) {
        const int match = (best >= TH) ? bi : -1;   // u >= 1/3 <=> iou >= 0.5

        const float aw = p.z - p.x, ah = p.w - p.y;
        const float ax = p.x + 0.5f * aw, ay = p.y + 0.5f * ah;
        const float raw = __fdividef(1.0f, aw), rah = __fdividef(1.0f, ah);

        const float4 mg = s_g[match < 0 ? 0 : match];
        const float gw = fmaxf(mg.z - mg.x, 1.0f);
        const float gh = fmaxf(mg.w - mg.y, 1.0f);
        const float gx = mg.x + 0.5f * gw, gy = mg.y + 0.5f * gh;

        float4 tgt;
        tgt.x = (gx - ax) * raw * 10.0f;
        tgt.y = (gy - ay) * rah * 10.0f;
        tgt.z = __logf(gw * raw) * 5.0f;
        tgt.w = __logf(gh * rah) * 5.0f;

        const float4 d = deltas[idx];
        const float cx = ax + (d.x * 0.1f) * aw;
        const float cy = ay + (d.y * 0.1f) * ah;
        const float ww = __expf(d.z * 0.2f) * aw;
        const float hh = __expf(d.w * 0.2f) * ah;

        float4 dec;
        dec.x = cx - 0.5f * ww;
        dec.y = cy - 0.5f * hh;
        dec.z = cx + 0.5f * ww;
        dec.w = cy + 0.5f * hh;

        out_decoded[idx] = dec;
        out_targets[idx] = tgt;
        out_matches[idx] = (float)match;
    }
}

extern "C" void kernel_launch(void* const* d_in, const int* in_sizes, int n_in,
                              void* d_out, int out_size)
{
    const float4* proposals = (const float4*)d_in[0];
    const float4* gt_boxes  = (const float4*)d_in[1];
    const float4* deltas    = (const float4*)d_in[2];

    const int B = in_sizes[1] / (M_GT * 4);
    const int N = in_sizes[0] / (B * 4);

    float* out = (float*)d_out;
    float4* out_decoded = (float4*)out;
    float4* out_targets = (float4*)(out + (long)B * N * 4);
    float*  out_matches = out + 2L * B * N * 4;

    dim3 grid((N + BLOCK - 1) / BLOCK, B);
    roihead_kernel<<<grid, BLOCK>>>(proposals, gt_boxes, deltas,
                                    out_decoded, out_targets, out_matches, N);
}

// round 8
// speedup vs baseline: 1.0344x; 1.0344x over previous
#include <cuda_runtime.h>
#include <cuda_bf16.h>

static constexpr int M_GT = 64;
static constexpr int BLOCK = 128;
#define TH (1.0f / 3.0f)   // iou >= 0.5  <=>  u = inter/S >= 1/3

__global__ void __launch_bounds__(BLOCK, 12)
roihead_kernel(const float4* __restrict__ proposals,   // [B, N] float4
               const float4* __restrict__ gt_boxes,    // [B, 64] float4
               const float4* __restrict__ deltas,      // [B, N] float4
               float4* __restrict__ out_decoded,
               float4* __restrict__ out_targets,
               float*  __restrict__ out_matches,
               int N)
{
    __shared__ float4 s_g[M_GT];
    __shared__ float  s_area[M_GT];

    const int b = blockIdx.y;

    if (threadIdx.x < M_GT) {
        float4 g = gt_boxes[b * M_GT + threadIdx.x];
        s_g[threadIdx.x] = g;
        s_area[threadIdx.x] = (g.z - g.x) * (g.w - g.y);
    }
    __syncthreads();

    // Lane pair (2m, 2m+1) cooperates on proposals n0=2m, n1=2m+1.
    // h selects the interleaved gt subset g = 2i+h (2-address broadcast LDS).
    const int t = blockIdx.x * BLOCK + threadIdx.x;
    const int m = t >> 1;
    const int h = t & 1;

    const int n0 = 2 * m;
    const int n1 = 2 * m + 1;
    const bool v0 = (n0 < N);
    const bool v1 = (n1 < N);

    const long base = (long)b * N;
    const long idx0 = base + (v0 ? n0 : 0);
    const long idx1 = base + (v1 ? n1 : 0);

    const float4 p0 = proposals[idx0];
    const float4 p1 = proposals[idx1];
    const float areap0 = (p0.z - p0.x) * (p0.w - p0.y);
    const float areap1 = (p1.z - p1.x) * (p1.w - p1.y);

    float best0 = -1.0f, best1 = -1.0f;
    int   bi0   = 0,     bi1   = 0;

#pragma unroll 16
    for (int i = 0; i < M_GT / 2; ++i) {
        const int g = 2 * i + h;
        const float4 gb = s_g[g];
        const float  ag = s_area[g];

        {   // proposal n0 : u = inter / (area_g + area_p)  (monotone in iou)
            const float iw = fminf(gb.z, p0.z) - fmaxf(gb.x, p0.x);   // unclamped (safe, R4)
            const float ih = fmaxf(fminf(gb.w, p0.w) - fmaxf(gb.y, p0.y), 0.0f);
            const float u  = __fdividef(iw * ih, ag + areap0);
            if (u > best0) { best0 = u; bi0 = g; }    // full-precision first-max
        }
        {   // proposal n1
            const float iw = fminf(gb.z, p1.z) - fmaxf(gb.x, p1.x);
            const float ih = fmaxf(fminf(gb.w, p1.w) - fmaxf(gb.y, p1.y), 0.0f);
            const float u  = __fdividef(iw * ih, ag + areap1);
            if (u > best1) { best1 = u; bi1 = g; }
        }
    }

    // Merge across the lane pair (exact first-max: tie -> lower g).
    {
        const float ob  = __shfl_xor_sync(0xFFFFFFFFu, best0, 1);
        const int   obi = __shfl_xor_sync(0xFFFFFFFFu, bi0,   1);
        if (ob > best0 || (ob == best0 && obi < bi0)) { best0 = ob; bi0 = obi; }
    }
    {
        const float ob  = __shfl_xor_sync(0xFFFFFFFFu, best1, 1);
        const int   obi = __shfl_xor_sync(0xFFFFFFFFu, bi1,   1);
        if (ob > best1 || (ob == best1 && obi < bi1)) { best1 = ob; bi1 = obi; }
    }

    // Convergent epilogue: lane h writes proposal n_h.
    const float4 p    = h ? p1    : p0;
    const float  best = h ? best1 : best0;
    const int    bi   = h ? bi1   : bi0;
    const long   idx  = h ? idx1  : idx0;
    const bool   v    = h ? v1    : v0;

    if (v) {
        const int match = (best >= TH) ? bi : -1;   // u >= 1/3 <=> iou >= 0.5

        const float aw = p.z - p.x, ah = p.w - p.y;
        const float ax = p.x + 0.5f * aw, ay = p.y + 0.5f * ah;
        const float raw = __fdividef(1.0f, aw), rah = __fdividef(1.0f, ah);

        const float4 mg = s_g[match < 0 ? 0 : match];
        const float gw = fmaxf(mg.z - mg.x, 1.0f);
        const float gh = fmaxf(mg.w - mg.y, 1.0f);
        const float gx = mg.x + 0.5f * gw, gy = mg.y + 0.5f * gh;

        float4 tgt;
        tgt.x = (gx - ax) * raw * 10.0f;
        tgt.y = (gy - ay) * rah * 10.0f;
        tgt.z = __logf(gw * raw) * 5.0f;
        tgt.w = __logf(gh * rah) * 5.0f;

        const float4 d = deltas[idx];
        const float cx = ax + (d.x * 0.1f) * aw;
        const float cy = ay + (d.y * 0.1f) * ah;
        const float ww = __expf(d.z * 0.2f) * aw;
        const float hh = __expf(d.w * 0.2f) * ah;

        float4 dec;
        dec.x = cx - 0.5f * ww;
        dec.y = cy - 0.5f * hh;
        dec.z = cx + 0.5f * ww;
        dec.w = cy + 0.5f * hh;

        out_decoded[idx] = dec;
        out_targets[idx] = tgt;
        out_matches[idx] = (float)match;
    }
}

extern "C" void kernel_launch(void* const* d_in, const int* in_sizes, int n_in,
                              void* d_out, int out_size)
{
    const float4* proposals = (const float4*)d_in[0];
    const float4* gt_boxes  = (const float4*)d_in[1];
    const float4* deltas    = (const float4*)d_in[2];

    const int B = in_sizes[1] / (M_GT * 4);
    const int N = in_sizes[0] / (B * 4);

    float* out = (float*)d_out;
    float4* out_decoded = (float4*)out;
    float4* out_targets = (float4*)(out + (long)B * N * 4);
    float*  out_matches = out + 2L * B * N * 4;

    // one thread per proposal (lane pairs share two proposals); fine-grained CTAs
    dim3 grid((N + BLOCK - 1) / BLOCK, B);
    roihead_kernel<<<grid, BLOCK>>>(proposals, gt_boxes, deltas,
                                    out_decoded, out_targets, out_matches, N);
}

// round 9
// speedup vs baseline: 1.0459x; 1.0111x over previous
#include <cuda_runtime.h>
#include <cuda_bf16.h>

static constexpr int M_GT = 64;
static constexpr int BLOCK = 128;
#define TH (1.0f / 3.0f)   // iou >= 0.5  <=>  u = inter/S >= 1/3

__global__ void __launch_bounds__(BLOCK, 12)
roihead_kernel(const float4* __restrict__ proposals,   // [B, N] float4
               const float4* __restrict__ gt_boxes,    // [B, 64] float4
               const float4* __restrict__ deltas,      // [B, N] float4
               float4* __restrict__ out_decoded,
               float4* __restrict__ out_targets,
               float*  __restrict__ out_matches,
               int N)
{
    __shared__ float4 s_g[M_GT];
    __shared__ float  s_area[M_GT];

    const int b = blockIdx.y;

    if (threadIdx.x < M_GT) {
        float4 g = gt_boxes[b * M_GT + threadIdx.x];
        s_g[threadIdx.x] = g;
        s_area[threadIdx.x] = (g.z - g.x) * (g.w - g.y);
    }
    __syncthreads();

    // Lane pair (2m, 2m+1) cooperates on proposals n0=2m, n1=2m+1.
    // h selects the interleaved gt subset g = 2i+h.
    const int t = blockIdx.x * BLOCK + threadIdx.x;
    const int m = t >> 1;
    const int h = t & 1;

    const int n0 = 2 * m;
    const int n1 = 2 * m + 1;
    const bool v0 = (n0 < N);
    const bool v1 = (n1 < N);

    const long base = (long)b * N;
    const long idx0 = base + (v0 ? n0 : 0);
    const long idx1 = base + (v1 ? n1 : 0);

    const float4 p0 = proposals[idx0];
    const float4 p1 = proposals[idx1];
    const float areap0 = (p0.z - p0.x) * (p0.w - p0.y);
    const float areap1 = (p1.z - p1.x) * (p1.w - p1.y);

    // Hoist the h offset into the pointers.
    const float4* __restrict__ gh = s_g    + h;
    const float*  __restrict__ ah = s_area + h;

    float best0 = -1.0f, best1 = -1.0f;
    int   bi0   = 0,     bi1   = 0;

#pragma unroll 32
    for (int i = 0; i < M_GT / 2; ++i) {
        const float4 gb = gh[2 * i];
        const float  ag = ah[2 * i];
        const int    g  = 2 * i + h;

        {   // proposal n0 : u = inter / (area_g + area_p)  (monotone in iou)
            const float iw = fminf(gb.z, p0.z) - fmaxf(gb.x, p0.x);   // unclamped (safe, R4)
            const float ih = fmaxf(fminf(gb.w, p0.w) - fmaxf(gb.y, p0.y), 0.0f);
            const float u  = __fdividef(iw * ih, ag + areap0);
            // Predicate kept OFF the loop-carried path:
            //   bi chain: SEL->SEL (4 cyc), best chain: FMNMX->FMNMX (4 cyc).
            bi0   = (u > best0) ? g : bi0;     // uses pre-update best (first-max on ties)
            best0 = fmaxf(best0, u);
        }
        {   // proposal n1
            const float iw = fminf(gb.z, p1.z) - fmaxf(gb.x, p1.x);
            const float ih = fmaxf(fminf(gb.w, p1.w) - fmaxf(gb.y, p1.y), 0.0f);
            const float u  = __fdividef(iw * ih, ag + areap1);
            bi1   = (u > best1) ? g : bi1;
            best1 = fmaxf(best1, u);
        }
    }

    // Merge across the lane pair (exact first-max: tie -> lower g).
    {
        const float ob  = __shfl_xor_sync(0xFFFFFFFFu, best0, 1);
        const int   obi = __shfl_xor_sync(0xFFFFFFFFu, bi0,   1);
        if (ob > best0 || (ob == best0 && obi < bi0)) { bi0 = obi; }
        best0 = fmaxf(best0, ob);
    }
    {
        const float ob  = __shfl_xor_sync(0xFFFFFFFFu, best1, 1);
        const int   obi = __shfl_xor_sync(0xFFFFFFFFu, bi1,   1);
        if (ob > best1 || (ob == best1 && obi < bi1)) { bi1 = obi; }
        best1 = fmaxf(best1, ob);
    }

    // Convergent epilogue: lane h writes proposal n_h.
    const float4 p    = h ? p1    : p0;
    const float  best = h ? best1 : best0;
    const int    bi   = h ? bi1   : bi0;
    const long   idx  = h ? idx1  : idx0;
    const bool   v    = h ? v1    : v0;

    if (v) {
        const int match = (best >= TH) ? bi : -1;   // u >= 1/3 <=> iou >= 0.5

        const float aw = p.z - p.x, ah2 = p.w - p.y;
        const float ax = p.x + 0.5f * aw, ay = p.y + 0.5f * ah2;
        const float raw = __fdividef(1.0f, aw), rah = __fdividef(1.0f, ah2);

        const float4 mg = s_g[match < 0 ? 0 : match];
        const float gw = fmaxf(mg.z - mg.x, 1.0f);
        const float gh2 = fmaxf(mg.w - mg.y, 1.0f);
        const float gx = mg.x + 0.5f * gw, gy = mg.y + 0.5f * gh2;

        float4 tgt;
        tgt.x = (gx - ax) * raw * 10.0f;
        tgt.y = (gy - ay) * rah * 10.0f;
        tgt.z = __logf(gw * raw) * 5.0f;
        tgt.w = __logf(gh2 * rah) * 5.0f;

        const float4 d = deltas[idx];
        const float cx = ax + (d.x * 0.1f) * aw;
        const float cy = ay + (d.y * 0.1f) * ah2;
        const float ww = __expf(d.z * 0.2f) * aw;
        const float hh = __expf(d.w * 0.2f) * ah2;

        float4 dec;
        dec.x = cx - 0.5f * ww;
        dec.y = cy - 0.5f * hh;
        dec.z = cx + 0.5f * ww;
        dec.w = cy + 0.5f * hh;

        out_decoded[idx] = dec;
        out_targets[idx] = tgt;
        out_matches[idx] = (float)match;
    }
}

extern "C" void kernel_launch(void* const* d_in, const int* in_sizes, int n_in,
                              void* d_out, int out_size)
{
    const float4* proposals = (const float4*)d_in[0];
    const float4* gt_boxes  = (const float4*)d_in[1];
    const float4* deltas    = (const float4*)d_in[2];

    const int B = in_sizes[1] / (M_GT * 4);
    const int N = in_sizes[0] / (B * 4);

    float* out = (float*)d_out;
    float4* out_decoded = (float4*)out;
    float4* out_targets = (float4*)(out + (long)B * N * 4);
    float*  out_matches = out + 2L * B * N * 4;

    dim3 grid((N + BLOCK - 1) / BLOCK, B);
    roihead_kernel<<<grid, BLOCK>>>(proposals, gt_boxes, deltas,
                                    out_decoded, out_targets, out_matches, N);
}